// round 15
// baseline (speedup 1.0000x reference)
#include <cuda_runtime.h>
#include <cuda_fp16.h>
#include <cstdint>
#include <math.h>

#define TOKENS 36864
#define PS 768
#define HID 1536

#define BM 128
#define BN 128
#define BKH 64                 // K halves per stage (128 B rows)
#define NST 3
#define ROWB 128
#define STAGE_BYTES ((BM + BN) * ROWB)        // 32768
#define SMEM_BYTES (NST * STAGE_BYTES)        // 98304
#define GTHREADS 128           // 4 warps per CTA, warp tile 64x64 (2m x 2n)

// Scratch (device globals — allocation guards forbid cudaMalloc)
__device__ __half g_Y[(size_t)TOKENS * PS];     // LN'd patches, fp16, k-permuted
__device__ __half g_H[(size_t)TOKENS * HID];    // hidden acts, fp16, k-permuted
__device__ __half g_W1T[(size_t)HID * PS];      // w1^T [1536,768], k-permuted
__device__ __half g_W2T[(size_t)PS * HID];      // w2^T [768,1536], k-permuted

// k-permutation within 32-blocks: k=(q,h,t,i) -> pos = t*8 + q*4 + h*2 + i
__device__ __forceinline__ int permk32(int k) {
    return (k & ~31) | ((k & 6) << 2) | (((k >> 4) & 1) << 2)
         | (((k >> 3) & 1) << 1) | (k & 1);
}
__device__ __forceinline__ uint32_t smem_u32(const void* p) {
    uint32_t a;
    asm("{ .reg .u64 t; cvta.to.shared.u64 t, %1; cvt.u32.u64 %0, t; }" : "=r"(a) : "l"(p));
    return a;
}
__device__ __forceinline__ void cp_async16(uint32_t dst, const void* src) {
    asm volatile("cp.async.cg.shared.global [%0], [%1], 16;\n" :: "r"(dst), "l"(src));
}
__device__ __forceinline__ void cp_commit() { asm volatile("cp.async.commit_group;\n" ::: "memory"); }
__device__ __forceinline__ void cp_wait1()  { asm volatile("cp.async.wait_group 1;\n" ::: "memory"); }
__device__ __forceinline__ void cp_wait0()  { asm volatile("cp.async.wait_group 0;\n" ::: "memory"); }

__device__ __forceinline__ void mma_f16(float* d, uint32_t a0, uint32_t a1,
                                        uint32_t a2, uint32_t a3,
                                        uint32_t b0, uint32_t b1) {
    asm volatile(
        "mma.sync.aligned.m16n8k16.row.col.f32.f16.f16.f32 "
        "{%0,%1,%2,%3}, {%4,%5,%6,%7}, {%8,%9}, {%0,%1,%2,%3};"
        : "+f"(d[0]), "+f"(d[1]), "+f"(d[2]), "+f"(d[3])
        : "r"(a0), "r"(a1), "r"(a2), "r"(a3), "r"(b0), "r"(b1));
}

// Fast exact GELU: 0.5x(1+erf(x/sqrt2)), erf via A&S 7.1.26 (|err|<=1.5e-7)
__device__ __forceinline__ float gelu_fast(float v) {
    const float z = fabsf(v) * 0.70710678118654752f;
    const float t = __fdividef(1.0f, fmaf(0.3275911f, z, 1.0f));
    float p = fmaf(t, 1.061405429f, -1.453152027f);
    p = fmaf(t, p, 1.421413741f);
    p = fmaf(t, p, -0.284496736f);
    p = fmaf(t, p, 0.254829592f);
    p *= t;
    const float e = __expf(-z * z);
    const float erfa = fmaf(-p, e, 1.0f);
    const float erfv = copysignf(erfa, v);
    return 0.5f * v * (1.0f + erfv);
}

// ---------------------------------------------------------------------------
// Kernel 1: unfold + LayerNorm -> fp16, k-permuted
// ---------------------------------------------------------------------------
__global__ void patch_ln_kernel(const float* __restrict__ x,
                                const float* __restrict__ ln_w,
                                const float* __restrict__ ln_b) {
    const int token = blockIdx.x;
    const int b  = token / 576;
    const int l  = token - b * 576;
    const int hp = l / 24;
    const int wp = l - hp * 24;
    const int t  = threadIdx.x;

    float v[3];
#pragma unroll
    for (int i = 0; i < 3; ++i) {
        const int p   = t + i * 256;
        const int c   = p >> 8;
        const int rem = p & 255;
        const int ph  = rem >> 4;
        const int pw  = rem & 15;
        const int xi  = ((b * 3 + c) * 384 + hp * 16 + ph) * 384 + wp * 16 + pw;
        v[i] = x[xi];
    }
    float s  = v[0] + v[1] + v[2];
    float sq = v[0] * v[0] + v[1] * v[1] + v[2] * v[2];
#pragma unroll
    for (int o = 16; o > 0; o >>= 1) {
        s  += __shfl_xor_sync(0xffffffffu, s, o);
        sq += __shfl_xor_sync(0xffffffffu, sq, o);
    }
    __shared__ float red_s[8], red_q[8];
    const int warp = t >> 5, lane = t & 31;
    if (lane == 0) { red_s[warp] = s; red_q[warp] = sq; }
    __syncthreads();
    float tot = 0.f, totq = 0.f;
#pragma unroll
    for (int i = 0; i < 8; ++i) { tot += red_s[i]; totq += red_q[i]; }
    const float mu  = tot * (1.0f / 768.0f);
    const float var = totq * (1.0f / 768.0f) - mu * mu;
    const float inv = rsqrtf(var + 1e-5f);

    __half* yrow = g_Y + (size_t)token * PS;
#pragma unroll
    for (int i = 0; i < 3; ++i) {
        const int p = t + i * 256;
        yrow[permk32(p)] = __float2half_rn((v[i] - mu) * inv * ln_w[p] + ln_b[p]);
    }
}

// ---------------------------------------------------------------------------
// Transpose: src [R,C] fp32 -> dst [C,R] fp16, K dim (rows of dst) permuted
// ---------------------------------------------------------------------------
template <int WHICH>
__global__ void transpose_kernel(const float* __restrict__ src, int R, int C) {
    __half* __restrict__ dst = (WHICH == 0) ? g_W1T : g_W2T;
    __shared__ float t[32][33];
    const int bx = blockIdx.x * 32, by = blockIdx.y * 32;
    const int x = threadIdx.x, y = threadIdx.y;
#pragma unroll
    for (int i = 0; i < 32; i += 8)
        t[y + i][x] = src[(size_t)(by + y + i) * C + bx + x];
    __syncthreads();
#pragma unroll
    for (int i = 0; i < 32; i += 8)
        dst[(size_t)(bx + y + i) * R + permk32(by + x)] = __float2half_rn(t[x][y + i]);
}

// ---------------------------------------------------------------------------
// FP16 mma.sync GEMM: CTA 128x128, 4 warps (2m x 2n), warp tile 64x64,
// m16n8k16, BK=64, 3-stage cp.async (wait1), ADD-swizzled smem, LDS.128.
// Inner MMA block software-pipelined: k-low sweep over all 32 accumulators,
// then k-high sweep -> dependent pairs separated by 31 independent MMAs.
// EPI 0: C = fp16(gelu(C+bias)) -> g_H (k-permuted cols)
// EPI 1: C = C+bias, fold + residual x -> out (fp32)
// ---------------------------------------------------------------------------
template <int NGL, int K, int EPI>
__global__ __launch_bounds__(GTHREADS, 2) void mma_gemm_kernel(
        const float* __restrict__ bias,
        const float* __restrict__ x,
        float* __restrict__ out) {
    extern __shared__ char smem[];
    const __half* __restrict__ A  = (EPI == 0) ? g_Y : g_H;
    const __half* __restrict__ Bt = (EPI == 0) ? g_W1T : g_W2T;

    const int tid  = threadIdx.x;
    const int lane = tid & 31;
    const int wid  = tid >> 5;
    const int wm   = wid & 1;        // 0..1 -> 64-row band
    const int wn   = wid >> 1;       // 0..1 -> 64-col band
    const int g    = lane >> 2;
    const int tig  = lane & 3;
    const int mBase = blockIdx.y * BM;
    const int nBase = blockIdx.x * BN;

    const uint32_t sbase = smem_u32(smem);

    // cp.async: A 1024 + B 1024 chunks (16B) per stage; 16 per thread
    const int r0 = tid >> 3;       // base row 0..15 (row parity const: +16i)
    const int j0 = tid & 7;        // source chunk within 128B k-row
    const __half* gA0 = A  + (size_t)(mBase + r0) * K + j0 * 8;
    const __half* gB0 = Bt + (size_t)(nBase + r0) * K + j0 * 8;
    const uint32_t dchunk = (uint32_t)((j0 + 4 * (r0 & 1)) & 7);
    const uint32_t dA0 = (uint32_t)r0 * ROWB + dchunk * 16u;

    auto load_stage = [&](int slot, int ks) {
        const uint32_t sb = sbase + (uint32_t)slot * STAGE_BYTES;
        const int ko = ks * BKH;
#pragma unroll
        for (int i = 0; i < 8; ++i)
            cp_async16(sb + dA0 + i * (16u * ROWB), gA0 + (size_t)(16 * i) * K + ko);
#pragma unroll
        for (int i = 0; i < 8; ++i)
            cp_async16(sb + (uint32_t)(BM * ROWB) + dA0 + i * (16u * ROWB),
                       gB0 + (size_t)(16 * i) * K + ko);
        cp_commit();
    };

    float acc[4][8][4];
#pragma unroll
    for (int i = 0; i < 4; ++i)
#pragma unroll
        for (int j = 0; j < 8; ++j)
#pragma unroll
            for (int q = 0; q < 4; ++q) acc[i][j][q] = 0.f;

    // fragment read offsets: phys chunk = (qq*4 + tig + 4*(g&1)) & 7
    const int pa = g & 1;
    uint32_t ckq[2];
#pragma unroll
    for (int qq = 0; qq < 2; ++qq)
        ckq[qq] = (uint32_t)(((qq * 4 + tig + 4 * pa) & 7) * 16);
    const uint32_t aRow0 = (uint32_t)(wm * 64 + g) * ROWB;
    const uint32_t bRow0 = (uint32_t)(BM * ROWB) + (uint32_t)(wn * 64 + g) * ROWB;

    constexpr int KT = K / BKH;
    load_stage(0, 0);
    load_stage(1, 1);

    for (int kt = 0; kt < KT; ++kt) {
        if (kt + 1 < KT) cp_wait1(); else cp_wait0();
        __syncthreads();
        if (kt + 2 < KT) load_stage((kt + 2) % NST, kt + 2);

        const char* st = smem + (kt % NST) * STAGE_BYTES;
#pragma unroll
        for (int qq = 0; qq < 2; ++qq) {
            uint4 alo[4], ahi[4], bb[8];
#pragma unroll
            for (int mt = 0; mt < 4; ++mt) {
                alo[mt] = *(const uint4*)(st + aRow0 + (uint32_t)(mt * 16) * ROWB + ckq[qq]);
                ahi[mt] = *(const uint4*)(st + aRow0 + (uint32_t)(mt * 16 + 8) * ROWB + ckq[qq]);
            }
#pragma unroll
            for (int nt = 0; nt < 8; ++nt)
                bb[nt] = *(const uint4*)(st + bRow0 + (uint32_t)(nt * 8) * ROWB + ckq[qq]);
            // sweep 1: k-low half for ALL accumulators (independent MMAs)
#pragma unroll
            for (int mt = 0; mt < 4; ++mt)
#pragma unroll
                for (int nt = 0; nt < 8; ++nt)
                    mma_f16(acc[mt][nt], alo[mt].x, ahi[mt].x, alo[mt].y, ahi[mt].y,
                            bb[nt].x, bb[nt].y);
            // sweep 2: k-high half (each dependent MMA is 31 instructions
            // away from its RAW producer)
#pragma unroll
            for (int mt = 0; mt < 4; ++mt)
#pragma unroll
                for (int nt = 0; nt < 8; ++nt)
                    mma_f16(acc[mt][nt], alo[mt].z, ahi[mt].z, alo[mt].w, ahi[mt].w,
                            bb[nt].z, bb[nt].w);
        }
    }

    // ---------------- epilogue (per-nt invariants hoisted) ----------------
    int    pcol[8];      // EPI0: permuted col; EPI1: image col offset
    float2 bv[8];
#pragma unroll
    for (int nt = 0; nt < 8; ++nt) {
        const int col = nBase + wn * 64 + nt * 8 + 2 * tig;
        bv[nt] = make_float2(__ldg(&bias[col]), __ldg(&bias[col + 1]));
        if (EPI == 0) {
            pcol[nt] = permk32(col);
        } else {
            const int cg  = col >> 8;
            const int rem = col & 255;
            const int ph  = rem >> 4;
            const int pw  = rem & 15;
            pcol[nt] = cg * 147456 + ph * 384 + pw;
        }
    }
    // row band is 64-aligned and 576 = 9*64 -> bimg constant per warp
    const int rowBand = mBase + wm * 64;
    const int bimg = rowBand / 576;
    const int lb   = rowBand - bimg * 576;

#pragma unroll
    for (int mt = 0; mt < 4; ++mt) {
#pragma unroll
        for (int half = 0; half < 2; ++half) {
            const int row = rowBand + mt * 16 + g + half * 8;
            if (EPI == 0) {
                __half* hrow = g_H + (size_t)row * NGL;
#pragma unroll
                for (int nt = 0; nt < 8; ++nt) {
                    const float a0 = gelu_fast(acc[mt][nt][half * 2 + 0] + bv[nt].x);
                    const float a1 = gelu_fast(acc[mt][nt][half * 2 + 1] + bv[nt].y);
                    *(__half2*)(hrow + pcol[nt]) = __floats2half2_rn(a0, a1);
                }
            } else {
                const int l  = lb + mt * 16 + g + half * 8;
                const int hp = l / 24;
                const int wp = l - hp * 24;
                const size_t rowOff = (size_t)bimg * 442368 + hp * 6144 + wp * 16;
#pragma unroll
                for (int nt = 0; nt < 8; ++nt) {
                    const size_t oi = rowOff + (size_t)pcol[nt];
                    const float2 xv = *(const float2*)(x + oi);
                    float2 v;
                    v.x = xv.x + acc[mt][nt][half * 2 + 0] + bv[nt].x;
                    v.y = xv.y + acc[mt][nt][half * 2 + 1] + bv[nt].y;
                    *(float2*)(out + oi) = v;
                }
            }
        }
    }
}

extern "C" void kernel_launch(void* const* d_in, const int* in_sizes, int n_in,
                              void* d_out, int out_size) {
    const float* x    = (const float*)d_in[0];
    const float* ln_w = (const float*)d_in[1];
    const float* ln_b = (const float*)d_in[2];
    const float* w1   = (const float*)d_in[3];
    const float* b1   = (const float*)d_in[4];
    const float* w2   = (const float*)d_in[5];
    const float* b2   = (const float*)d_in[6];
    float* out        = (float*)d_out;

    static bool configured = false;
    if (!configured) {
        cudaFuncSetAttribute(mma_gemm_kernel<HID, PS, 0>,
                             cudaFuncAttributeMaxDynamicSharedMemorySize, SMEM_BYTES);
        cudaFuncSetAttribute(mma_gemm_kernel<PS, HID, 1>,
                             cudaFuncAttributeMaxDynamicSharedMemorySize, SMEM_BYTES);
        configured = true;
    }

    dim3 tb(32, 8);
    transpose_kernel<0><<<dim3(HID / 32, PS / 32), tb>>>(w1, PS, HID);
    transpose_kernel<1><<<dim3(PS / 32, HID / 32), tb>>>(w2, HID, PS);

    patch_ln_kernel<<<TOKENS, 256>>>(x, ln_w, ln_b);

    dim3 g1(HID / BN, TOKENS / BM);   // (12, 288)
    mma_gemm_kernel<HID, PS, 0><<<g1, GTHREADS, SMEM_BYTES>>>(b1, nullptr, nullptr);

    dim3 g2(PS / BN, TOKENS / BM);    // (6, 288)
    mma_gemm_kernel<PS, HID, 1><<<g2, GTHREADS, SMEM_BYTES>>>(b2, x, out);
}

// round 16
// speedup vs baseline: 1.0364x; 1.0364x over previous
#include <cuda_runtime.h>
#include <cuda_fp16.h>
#include <cstdint>
#include <math.h>

#define TOKENS 36864
#define PS 768
#define HID 1536

#define BM 128
#define BN 128
#define BKH 64                 // K halves per stage (128 B rows)
#define NST 3
#define ROWB 128
#define STAGE_BYTES ((BM + BN) * ROWB)        // 32768
#define SMEM_BYTES (NST * STAGE_BYTES)        // 98304
#define GTHREADS 128           // 4 warps per CTA, warp tile 64x64 (2m x 2n)
#define MTILES 2               // m-tiles per CTA (amortize prologue/epilogue)

// Scratch (device globals — allocation guards forbid cudaMalloc)
__device__ __half g_Y[(size_t)TOKENS * PS];     // LN'd patches, fp16, k-permuted
__device__ __half g_H[(size_t)TOKENS * HID];    // hidden acts, fp16, k-permuted
__device__ __half g_W1T[(size_t)HID * PS];      // w1^T [1536,768], k-permuted
__device__ __half g_W2T[(size_t)PS * HID];      // w2^T [768,1536], k-permuted

// k-permutation within 32-blocks: k=(q,h,t,i) -> pos = t*8 + q*4 + h*2 + i
__device__ __forceinline__ int permk32(int k) {
    return (k & ~31) | ((k & 6) << 2) | (((k >> 4) & 1) << 2)
         | (((k >> 3) & 1) << 1) | (k & 1);
}
__device__ __forceinline__ uint32_t smem_u32(const void* p) {
    uint32_t a;
    asm("{ .reg .u64 t; cvta.to.shared.u64 t, %1; cvt.u32.u64 %0, t; }" : "=r"(a) : "l"(p));
    return a;
}
__device__ __forceinline__ void cp_async16(uint32_t dst, const void* src) {
    asm volatile("cp.async.cg.shared.global [%0], [%1], 16;\n" :: "r"(dst), "l"(src));
}
__device__ __forceinline__ void cp_commit() { asm volatile("cp.async.commit_group;\n" ::: "memory"); }
__device__ __forceinline__ void cp_wait1()  { asm volatile("cp.async.wait_group 1;\n" ::: "memory"); }
__device__ __forceinline__ void cp_wait0()  { asm volatile("cp.async.wait_group 0;\n" ::: "memory"); }

__device__ __forceinline__ void mma_f16(float* d, uint32_t a0, uint32_t a1,
                                        uint32_t a2, uint32_t a3,
                                        uint32_t b0, uint32_t b1) {
    asm volatile(
        "mma.sync.aligned.m16n8k16.row.col.f32.f16.f16.f32 "
        "{%0,%1,%2,%3}, {%4,%5,%6,%7}, {%8,%9}, {%0,%1,%2,%3};"
        : "+f"(d[0]), "+f"(d[1]), "+f"(d[2]), "+f"(d[3])
        : "r"(a0), "r"(a1), "r"(a2), "r"(a3), "r"(b0), "r"(b1));
}

// Fast exact GELU: 0.5x(1+erf(x/sqrt2)), erf via A&S 7.1.26 (|err|<=1.5e-7)
__device__ __forceinline__ float gelu_fast(float v) {
    const float z = fabsf(v) * 0.70710678118654752f;
    const float t = __fdividef(1.0f, fmaf(0.3275911f, z, 1.0f));
    float p = fmaf(t, 1.061405429f, -1.453152027f);
    p = fmaf(t, p, 1.421413741f);
    p = fmaf(t, p, -0.284496736f);
    p = fmaf(t, p, 0.254829592f);
    p *= t;
    const float e = __expf(-z * z);
    const float erfa = fmaf(-p, e, 1.0f);
    const float erfv = copysignf(erfa, v);
    return 0.5f * v * (1.0f + erfv);
}

// ---------------------------------------------------------------------------
// Kernel 1: unfold + LayerNorm -> fp16, k-permuted
// ---------------------------------------------------------------------------
__global__ void patch_ln_kernel(const float* __restrict__ x,
                                const float* __restrict__ ln_w,
                                const float* __restrict__ ln_b) {
    const int token = blockIdx.x;
    const int b  = token / 576;
    const int l  = token - b * 576;
    const int hp = l / 24;
    const int wp = l - hp * 24;
    const int t  = threadIdx.x;

    float v[3];
#pragma unroll
    for (int i = 0; i < 3; ++i) {
        const int p   = t + i * 256;
        const int c   = p >> 8;
        const int rem = p & 255;
        const int ph  = rem >> 4;
        const int pw  = rem & 15;
        const int xi  = ((b * 3 + c) * 384 + hp * 16 + ph) * 384 + wp * 16 + pw;
        v[i] = x[xi];
    }
    float s  = v[0] + v[1] + v[2];
    float sq = v[0] * v[0] + v[1] * v[1] + v[2] * v[2];
#pragma unroll
    for (int o = 16; o > 0; o >>= 1) {
        s  += __shfl_xor_sync(0xffffffffu, s, o);
        sq += __shfl_xor_sync(0xffffffffu, sq, o);
    }
    __shared__ float red_s[8], red_q[8];
    const int warp = t >> 5, lane = t & 31;
    if (lane == 0) { red_s[warp] = s; red_q[warp] = sq; }
    __syncthreads();
    float tot = 0.f, totq = 0.f;
#pragma unroll
    for (int i = 0; i < 8; ++i) { tot += red_s[i]; totq += red_q[i]; }
    const float mu  = tot * (1.0f / 768.0f);
    const float var = totq * (1.0f / 768.0f) - mu * mu;
    const float inv = rsqrtf(var + 1e-5f);

    __half* yrow = g_Y + (size_t)token * PS;
#pragma unroll
    for (int i = 0; i < 3; ++i) {
        const int p = t + i * 256;
        yrow[permk32(p)] = __float2half_rn((v[i] - mu) * inv * ln_w[p] + ln_b[p]);
    }
}

// ---------------------------------------------------------------------------
// Transpose: src [R,C] fp32 -> dst [C,R] fp16, K dim (rows of dst) permuted
// ---------------------------------------------------------------------------
template <int WHICH>
__global__ void transpose_kernel(const float* __restrict__ src, int R, int C) {
    __half* __restrict__ dst = (WHICH == 0) ? g_W1T : g_W2T;
    __shared__ float t[32][33];
    const int bx = blockIdx.x * 32, by = blockIdx.y * 32;
    const int x = threadIdx.x, y = threadIdx.y;
#pragma unroll
    for (int i = 0; i < 32; i += 8)
        t[y + i][x] = src[(size_t)(by + y + i) * C + bx + x];
    __syncthreads();
#pragma unroll
    for (int i = 0; i < 32; i += 8)
        dst[(size_t)(bx + y + i) * R + permk32(by + x)] = __float2half_rn(t[x][y + i]);
}

// ---------------------------------------------------------------------------
// FP16 mma.sync GEMM: 4 warps (2m x 2n), warp tile 64x64, m16n8k16, BK=64,
// 3-stage cp.async (wait1), ADD-swizzled smem, LDS.128.
// Each CTA computes MTILES=2 stacked 128x128 tiles: one prologue, next tile's
// stages prefetched during the previous tile's epilogue (pipeline never drains).
// EPI 0: C = fp16(gelu(C+bias)) -> g_H (k-permuted cols)
// EPI 1: C = C+bias, fold + residual x -> out (fp32)
// ---------------------------------------------------------------------------
template <int NGL, int K, int EPI>
__global__ __launch_bounds__(GTHREADS, 2) void mma_gemm_kernel(
        const float* __restrict__ bias,
        const float* __restrict__ x,
        float* __restrict__ out) {
    extern __shared__ char smem[];
    const __half* __restrict__ A  = (EPI == 0) ? g_Y : g_H;
    const __half* __restrict__ Bt = (EPI == 0) ? g_W1T : g_W2T;

    const int tid  = threadIdx.x;
    const int lane = tid & 31;
    const int wid  = tid >> 5;
    const int wm   = wid & 1;        // 0..1 -> 64-row band
    const int wn   = wid >> 1;       // 0..1 -> 64-col band
    const int g    = lane >> 2;
    const int tig  = lane & 3;
    const int mBase = blockIdx.y * (BM * MTILES);
    const int nBase = blockIdx.x * BN;

    const uint32_t sbase = smem_u32(smem);

    // cp.async: A 1024 + B 1024 chunks (16B) per stage; 16 per thread
    const int r0 = tid >> 3;       // base row 0..15 (row parity const: +16i)
    const int j0 = tid & 7;        // source chunk within 128B k-row
    const __half* gA0 = A  + (size_t)(mBase + r0) * K + j0 * 8;
    const __half* gB0 = Bt + (size_t)(nBase + r0) * K + j0 * 8;
    const uint32_t dchunk = (uint32_t)((j0 + 4 * (r0 & 1)) & 7);
    const uint32_t dA0 = (uint32_t)r0 * ROWB + dchunk * 16u;

    constexpr int KT  = K / BKH;
    constexpr int GKT = KT * MTILES;

    // gks: global k-step (tile = gks/KT, ks = gks%KT)
    auto load_stage = [&](int slot, int gks) {
        const int tile = gks / KT;
        const int ks   = gks - tile * KT;
        const uint32_t sb = sbase + (uint32_t)slot * STAGE_BYTES;
        const __half* ga = gA0 + (size_t)tile * BM * K + ks * BKH;
        const __half* gb = gB0 + ks * BKH;
#pragma unroll
        for (int i = 0; i < 8; ++i)
            cp_async16(sb + dA0 + i * (16u * ROWB), ga + (size_t)(16 * i) * K);
#pragma unroll
        for (int i = 0; i < 8; ++i)
            cp_async16(sb + (uint32_t)(BM * ROWB) + dA0 + i * (16u * ROWB),
                       gb + (size_t)(16 * i) * K);
        cp_commit();
    };

    float acc[4][8][4];
#pragma unroll
    for (int i = 0; i < 4; ++i)
#pragma unroll
        for (int j = 0; j < 8; ++j)
#pragma unroll
            for (int q = 0; q < 4; ++q) acc[i][j][q] = 0.f;

    // fragment read offsets: phys chunk = (qq*4 + tig + 4*(g&1)) & 7
    const int pa = g & 1;
    uint32_t ckq[2];
#pragma unroll
    for (int qq = 0; qq < 2; ++qq)
        ckq[qq] = (uint32_t)(((qq * 4 + tig + 4 * pa) & 7) * 16);
    const uint32_t aRow0 = (uint32_t)(wm * 64 + g) * ROWB;
    const uint32_t bRow0 = (uint32_t)(BM * ROWB) + (uint32_t)(wn * 64 + g) * ROWB;

    // epilogue per-nt invariants (tile-independent)
    int    pcol[8];
    float2 bv[8];
#pragma unroll
    for (int nt = 0; nt < 8; ++nt) {
        const int col = nBase + wn * 64 + nt * 8 + 2 * tig;
        bv[nt] = make_float2(__ldg(&bias[col]), __ldg(&bias[col + 1]));
        if (EPI == 0) {
            pcol[nt] = permk32(col);
        } else {
            const int cg  = col >> 8;
            const int rem = col & 255;
            const int ph  = rem >> 4;
            const int pw  = rem & 15;
            pcol[nt] = cg * 147456 + ph * 384 + pw;
        }
    }

    load_stage(0, 0);
    load_stage(1, 1);
    int gk = 0;

    for (int tile = 0; tile < MTILES; ++tile) {
        for (int kt = 0; kt < KT; ++kt, ++gk) {
            if (gk + 1 < GKT) cp_wait1(); else cp_wait0();
            __syncthreads();
            if (gk + 2 < GKT) load_stage((gk + 2) % NST, gk + 2);

            const char* st = smem + (gk % NST) * STAGE_BYTES;
#pragma unroll
            for (int qq = 0; qq < 2; ++qq) {
                uint4 alo[4], ahi[4], bb[8];
#pragma unroll
                for (int mt = 0; mt < 4; ++mt) {
                    alo[mt] = *(const uint4*)(st + aRow0 + (uint32_t)(mt * 16) * ROWB + ckq[qq]);
                    ahi[mt] = *(const uint4*)(st + aRow0 + (uint32_t)(mt * 16 + 8) * ROWB + ckq[qq]);
                }
#pragma unroll
                for (int nt = 0; nt < 8; ++nt)
                    bb[nt] = *(const uint4*)(st + bRow0 + (uint32_t)(nt * 8) * ROWB + ckq[qq]);
#pragma unroll
                for (int mt = 0; mt < 4; ++mt)
#pragma unroll
                    for (int nt = 0; nt < 8; ++nt) {
                        mma_f16(acc[mt][nt], alo[mt].x, ahi[mt].x, alo[mt].y, ahi[mt].y,
                                bb[nt].x, bb[nt].y);
                        mma_f16(acc[mt][nt], alo[mt].z, ahi[mt].z, alo[mt].w, ahi[mt].w,
                                bb[nt].z, bb[nt].w);
                    }
            }
        }

        // ---- epilogue for this tile (next tile's loads already in flight) ----
        const int rowBand = mBase + tile * BM + wm * 64;
        const int bimg = rowBand / 576;      // 64-aligned band, 576 = 9*64
        const int lb   = rowBand - bimg * 576;

#pragma unroll
        for (int mt = 0; mt < 4; ++mt) {
#pragma unroll
            for (int half = 0; half < 2; ++half) {
                const int row = rowBand + mt * 16 + g + half * 8;
                if (EPI == 0) {
                    __half* hrow = g_H + (size_t)row * NGL;
#pragma unroll
                    for (int nt = 0; nt < 8; ++nt) {
                        const float a0 = gelu_fast(acc[mt][nt][half * 2 + 0] + bv[nt].x);
                        const float a1 = gelu_fast(acc[mt][nt][half * 2 + 1] + bv[nt].y);
                        *(__half2*)(hrow + pcol[nt]) = __floats2half2_rn(a0, a1);
                    }
                } else {
                    const int l  = lb + mt * 16 + g + half * 8;
                    const int hp = l / 24;
                    const int wp = l - hp * 24;
                    const size_t rowOff = (size_t)bimg * 442368 + hp * 6144 + wp * 16;
#pragma unroll
                    for (int nt = 0; nt < 8; ++nt) {
                        const size_t oi = rowOff + (size_t)pcol[nt];
                        const float2 xv = *(const float2*)(x + oi);
                        float2 v;
                        v.x = xv.x + acc[mt][nt][half * 2 + 0] + bv[nt].x;
                        v.y = xv.y + acc[mt][nt][half * 2 + 1] + bv[nt].y;
                        *(float2*)(out + oi) = v;
                    }
                }
            }
        }

        if (tile + 1 < MTILES) {
#pragma unroll
            for (int i = 0; i < 4; ++i)
#pragma unroll
                for (int j = 0; j < 8; ++j)
#pragma unroll
                    for (int q = 0; q < 4; ++q) acc[i][j][q] = 0.f;
        }
    }
}

extern "C" void kernel_launch(void* const* d_in, const int* in_sizes, int n_in,
                              void* d_out, int out_size) {
    const float* x    = (const float*)d_in[0];
    const float* ln_w = (const float*)d_in[1];
    const float* ln_b = (const float*)d_in[2];
    const float* w1   = (const float*)d_in[3];
    const float* b1   = (const float*)d_in[4];
    const float* w2   = (const float*)d_in[5];
    const float* b2   = (const float*)d_in[6];
    float* out        = (float*)d_out;

    static bool configured = false;
    if (!configured) {
        cudaFuncSetAttribute(mma_gemm_kernel<HID, PS, 0>,
                             cudaFuncAttributeMaxDynamicSharedMemorySize, SMEM_BYTES);
        cudaFuncSetAttribute(mma_gemm_kernel<PS, HID, 1>,
                             cudaFuncAttributeMaxDynamicSharedMemorySize, SMEM_BYTES);
        configured = true;
    }

    dim3 tb(32, 8);
    transpose_kernel<0><<<dim3(HID / 32, PS / 32), tb>>>(w1, PS, HID);
    transpose_kernel<1><<<dim3(PS / 32, HID / 32), tb>>>(w2, HID, PS);

    patch_ln_kernel<<<TOKENS, 256>>>(x, ln_w, ln_b);

    dim3 g1(HID / BN, TOKENS / (BM * MTILES));   // (12, 144)
    mma_gemm_kernel<HID, PS, 0><<<g1, GTHREADS, SMEM_BYTES>>>(b1, nullptr, nullptr);

    dim3 g2(PS / BN, TOKENS / (BM * MTILES));    // (6, 144)
    mma_gemm_kernel<PS, HID, 1><<<g2, GTHREADS, SMEM_BYTES>>>(b2, x, out);
}

// round 17
// speedup vs baseline: 1.1540x; 1.1135x over previous
#include <cuda_runtime.h>
#include <cuda_fp16.h>
#include <cstdint>
#include <math.h>

#define TOKENS 36864
#define PS 768
#define HID 1536

#define BM 128
#define BN 128
#define BKH 64                 // K halves per stage (128 B rows)
#define NST 3
#define ROWB 128
#define STAGE_BYTES ((BM + BN) * ROWB)        // 32768
#define SMEM_BYTES (NST * STAGE_BYTES)        // 98304
#define GTHREADS 128           // 4 warps per CTA, warp tile 64x64 (2m x 2n)

// Scratch (device globals — allocation guards forbid cudaMalloc)
__device__ __half g_Y[(size_t)TOKENS * PS];     // LN'd patches, fp16, k-permuted
__device__ __half g_H[(size_t)TOKENS * HID];    // hidden acts, fp16, k-permuted
__device__ __half g_W1T[(size_t)HID * PS];      // w1^T [1536,768], k-permuted
__device__ __half g_W2T[(size_t)PS * HID];      // w2^T [768,1536], k-permuted

// k-permutation within 32-blocks: k=(q,h,t,i) -> pos = t*8 + q*4 + h*2 + i
__device__ __forceinline__ int permk32(int k) {
    return (k & ~31) | ((k & 6) << 2) | (((k >> 4) & 1) << 2)
         | (((k >> 3) & 1) << 1) | (k & 1);
}
__device__ __forceinline__ uint32_t smem_u32(const void* p) {
    uint32_t a;
    asm("{ .reg .u64 t; cvta.to.shared.u64 t, %1; cvt.u32.u64 %0, t; }" : "=r"(a) : "l"(p));
    return a;
}
__device__ __forceinline__ void cp_async16(uint32_t dst, const void* src) {
    asm volatile("cp.async.cg.shared.global [%0], [%1], 16;\n" :: "r"(dst), "l"(src));
}
__device__ __forceinline__ void cp_commit() { asm volatile("cp.async.commit_group;\n" ::: "memory"); }
__device__ __forceinline__ void cp_wait1()  { asm volatile("cp.async.wait_group 1;\n" ::: "memory"); }
__device__ __forceinline__ void cp_wait0()  { asm volatile("cp.async.wait_group 0;\n" ::: "memory"); }

__device__ __forceinline__ void mma_f16(float* d, uint32_t a0, uint32_t a1,
                                        uint32_t a2, uint32_t a3,
                                        uint32_t b0, uint32_t b1) {
    asm volatile(
        "mma.sync.aligned.m16n8k16.row.col.f32.f16.f16.f32 "
        "{%0,%1,%2,%3}, {%4,%5,%6,%7}, {%8,%9}, {%0,%1,%2,%3};"
        : "+f"(d[0]), "+f"(d[1]), "+f"(d[2]), "+f"(d[3])
        : "r"(a0), "r"(a1), "r"(a2), "r"(a3), "r"(b0), "r"(b1));
}

// Fast exact GELU: 0.5x(1+erf(x/sqrt2)), erf via A&S 7.1.26 (|err|<=1.5e-7)
__device__ __forceinline__ float gelu_fast(float v) {
    const float z = fabsf(v) * 0.70710678118654752f;
    const float t = __fdividef(1.0f, fmaf(0.3275911f, z, 1.0f));
    float p = fmaf(t, 1.061405429f, -1.453152027f);
    p = fmaf(t, p, 1.421413741f);
    p = fmaf(t, p, -0.284496736f);
    p = fmaf(t, p, 0.254829592f);
    p *= t;
    const float e = __expf(-z * z);
    const float erfa = fmaf(-p, e, 1.0f);
    const float erfv = copysignf(erfa, v);
    return 0.5f * v * (1.0f + erfv);
}

// ---------------------------------------------------------------------------
// Kernel 1: unfold + LayerNorm -> fp16, k-permuted.
// One WARP per token: float4 loads, warp-shfl reduction, no block barrier.
// ---------------------------------------------------------------------------
__global__ __launch_bounds__(128) void patch_ln_kernel(
        const float* __restrict__ x,
        const float* __restrict__ ln_w,
        const float* __restrict__ ln_b) {
    const int lane  = threadIdx.x & 31;
    const int token = blockIdx.x * 4 + (threadIdx.x >> 5);
    const int b  = token / 576;
    const int l  = token - b * 576;
    const int hp = l / 24;
    const int wp = l - hp * 24;

    const float* xbase = x + ((size_t)b * 3) * 147456 + (size_t)hp * 6144 + wp * 16;

    float4 v[6];
#pragma unroll
    for (int i = 0; i < 6; ++i) {
        const int p  = i * 128 + lane * 4;
        const int c  = p >> 8;
        const int ph = (p >> 4) & 15;
        const int pw = p & 15;
        v[i] = *(const float4*)(xbase + (size_t)c * 147456 + ph * 384 + pw);
    }
    float s = 0.f, sq = 0.f;
#pragma unroll
    for (int i = 0; i < 6; ++i) {
        s  += v[i].x + v[i].y + v[i].z + v[i].w;
        sq += v[i].x * v[i].x + v[i].y * v[i].y + v[i].z * v[i].z + v[i].w * v[i].w;
    }
#pragma unroll
    for (int o = 16; o > 0; o >>= 1) {
        s  += __shfl_xor_sync(0xffffffffu, s, o);
        sq += __shfl_xor_sync(0xffffffffu, sq, o);
    }
    const float mu  = s * (1.0f / 768.0f);
    const float var = sq * (1.0f / 768.0f) - mu * mu;
    const float inv = rsqrtf(var + 1e-5f);

    __half* yrow = g_Y + (size_t)token * PS;
#pragma unroll
    for (int i = 0; i < 6; ++i) {
        const int p = i * 128 + lane * 4;
        const float4 w4 = __ldg((const float4*)(ln_w + p));
        const float4 b4 = __ldg((const float4*)(ln_b + p));
        const float f0 = (v[i].x - mu) * inv * w4.x + b4.x;
        const float f1 = (v[i].y - mu) * inv * w4.y + b4.y;
        const float f2 = (v[i].z - mu) * inv * w4.z + b4.z;
        const float f3 = (v[i].w - mu) * inv * w4.w + b4.w;
        *(__half2*)(yrow + permk32(p))     = __floats2half2_rn(f0, f1);
        *(__half2*)(yrow + permk32(p + 2)) = __floats2half2_rn(f2, f3);
    }
}

// ---------------------------------------------------------------------------
// Transpose: src [R,C] fp32 -> dst [C,R] fp16, K dim (rows of dst) permuted
// ---------------------------------------------------------------------------
template <int WHICH>
__global__ void transpose_kernel(const float* __restrict__ src, int R, int C) {
    __half* __restrict__ dst = (WHICH == 0) ? g_W1T : g_W2T;
    __shared__ float t[32][33];
    const int bx = blockIdx.x * 32, by = blockIdx.y * 32;
    const int x = threadIdx.x, y = threadIdx.y;
#pragma unroll
    for (int i = 0; i < 32; i += 8)
        t[y + i][x] = src[(size_t)(by + y + i) * C + bx + x];
    __syncthreads();
#pragma unroll
    for (int i = 0; i < 32; i += 8)
        dst[(size_t)(bx + y + i) * R + permk32(by + x)] = __float2half_rn(t[x][y + i]);
}

// ---------------------------------------------------------------------------
// FP16 mma.sync GEMM: CTA 128x128, 4 warps (2m x 2n), warp tile 64x64,
// m16n8k16, BK=64, 3-stage cp.async (wait1), ADD-swizzled smem, LDS.128.
// EPI 0: C = fp16(gelu(C+bias)) -> g_H via SMEM-STAGED COALESCED stores.
// EPI 1: C = C+bias, fold + residual x -> out (fp32)
// ---------------------------------------------------------------------------
template <int NGL, int K, int EPI>
__global__ __launch_bounds__(GTHREADS, 2) void mma_gemm_kernel(
        const float* __restrict__ bias,
        const float* __restrict__ x,
        float* __restrict__ out) {
    extern __shared__ char smem[];
    const __half* __restrict__ A  = (EPI == 0) ? g_Y : g_H;
    const __half* __restrict__ Bt = (EPI == 0) ? g_W1T : g_W2T;

    const int tid  = threadIdx.x;
    const int lane = tid & 31;
    const int wid  = tid >> 5;
    const int wm   = wid & 1;        // 0..1 -> 64-row band
    const int wn   = wid >> 1;       // 0..1 -> 64-col band
    const int g    = lane >> 2;
    const int tig  = lane & 3;
    const int mBase = blockIdx.y * BM;
    const int nBase = blockIdx.x * BN;

    const uint32_t sbase = smem_u32(smem);

    // cp.async: A 1024 + B 1024 chunks (16B) per stage; 16 per thread
    const int r0 = tid >> 3;       // base row 0..15 (row parity const: +16i)
    const int j0 = tid & 7;        // source chunk within 128B k-row
    const __half* gA0 = A  + (size_t)(mBase + r0) * K + j0 * 8;
    const __half* gB0 = Bt + (size_t)(nBase + r0) * K + j0 * 8;
    const uint32_t dchunk = (uint32_t)((j0 + 4 * (r0 & 1)) & 7);
    const uint32_t dA0 = (uint32_t)r0 * ROWB + dchunk * 16u;

    auto load_stage = [&](int slot, int ks) {
        const uint32_t sb = sbase + (uint32_t)slot * STAGE_BYTES;
        const int ko = ks * BKH;
#pragma unroll
        for (int i = 0; i < 8; ++i)
            cp_async16(sb + dA0 + i * (16u * ROWB), gA0 + (size_t)(16 * i) * K + ko);
#pragma unroll
        for (int i = 0; i < 8; ++i)
            cp_async16(sb + (uint32_t)(BM * ROWB) + dA0 + i * (16u * ROWB),
                       gB0 + (size_t)(16 * i) * K + ko);
        cp_commit();
    };

    float acc[4][8][4];
#pragma unroll
    for (int i = 0; i < 4; ++i)
#pragma unroll
        for (int j = 0; j < 8; ++j)
#pragma unroll
            for (int q = 0; q < 4; ++q) acc[i][j][q] = 0.f;

    // fragment read offsets: phys chunk = (qq*4 + tig + 4*(g&1)) & 7
    const int pa = g & 1;
    uint32_t ckq[2];
#pragma unroll
    for (int qq = 0; qq < 2; ++qq)
        ckq[qq] = (uint32_t)(((qq * 4 + tig + 4 * pa) & 7) * 16);
    const uint32_t aRow0 = (uint32_t)(wm * 64 + g) * ROWB;
    const uint32_t bRow0 = (uint32_t)(BM * ROWB) + (uint32_t)(wn * 64 + g) * ROWB;

    constexpr int KT = K / BKH;
    load_stage(0, 0);
    load_stage(1, 1);

    for (int kt = 0; kt < KT; ++kt) {
        if (kt + 1 < KT) cp_wait1(); else cp_wait0();
        __syncthreads();
        if (kt + 2 < KT) load_stage((kt + 2) % NST, kt + 2);

        const char* st = smem + (kt % NST) * STAGE_BYTES;
#pragma unroll
        for (int qq = 0; qq < 2; ++qq) {
            uint4 alo[4], ahi[4], bb[8];
#pragma unroll
            for (int mt = 0; mt < 4; ++mt) {
                alo[mt] = *(const uint4*)(st + aRow0 + (uint32_t)(mt * 16) * ROWB + ckq[qq]);
                ahi[mt] = *(const uint4*)(st + aRow0 + (uint32_t)(mt * 16 + 8) * ROWB + ckq[qq]);
            }
#pragma unroll
            for (int nt = 0; nt < 8; ++nt)
                bb[nt] = *(const uint4*)(st + bRow0 + (uint32_t)(nt * 8) * ROWB + ckq[qq]);
#pragma unroll
            for (int mt = 0; mt < 4; ++mt)
#pragma unroll
                for (int nt = 0; nt < 8; ++nt) {
                    mma_f16(acc[mt][nt], alo[mt].x, ahi[mt].x, alo[mt].y, ahi[mt].y,
                            bb[nt].x, bb[nt].y);
                    mma_f16(acc[mt][nt], alo[mt].z, ahi[mt].z, alo[mt].w, ahi[mt].w,
                            bb[nt].z, bb[nt].w);
                }
        }
    }

    if (EPI == 0) {
        // ---------- epilogue: gelu -> smem staging -> coalesced STG.128 ----------
        // physical position within the CTA's 128-col (256B) slab for (wn,nt,tig):
        //   16B chunk = wn*8 + (nt>>2)*4 + tig, 4B word = nt&3  (permk32-derived)
        float2 bv[8];
#pragma unroll
        for (int nt = 0; nt < 8; ++nt) {
            const int col = nBase + wn * 64 + nt * 8 + 2 * tig;
            bv[nt] = make_float2(__ldg(&bias[col]), __ldg(&bias[col + 1]));
        }
        __syncthreads();                       // mainloop smem reads done
#pragma unroll
        for (int mt = 0; mt < 4; ++mt) {
#pragma unroll
            for (int half = 0; half < 2; ++half) {
                const int srow = wm * 64 + mt * 16 + g + half * 8;  // 0..127
#pragma unroll
                for (int nt = 0; nt < 8; ++nt) {
                    const float a0 = gelu_fast(acc[mt][nt][half * 2 + 0] + bv[nt].x);
                    const float a1 = gelu_fast(acc[mt][nt][half * 2 + 1] + bv[nt].y);
                    const uint32_t cn = (uint32_t)((wn * 8 + (nt >> 2) * 4 + tig) ^ (srow & 7));
                    *(__half2*)(smem + srow * 256 + cn * 16 + (nt & 3) * 4) =
                        __floats2half2_rn(a0, a1);
                }
            }
        }
        __syncthreads();
        // coalesced copy out: 2048 16B chunks, 16 per thread
#pragma unroll
        for (int c = 0; c < 16; ++c) {
            const int id  = c * GTHREADS + tid;
            const int row = id >> 4;
            const int cc  = id & 15;
            const uint32_t ch = (uint32_t)(cc ^ (row & 7));
            const uint4 vv = *(const uint4*)(smem + row * 256 + ch * 16);
            *(uint4*)(g_H + (size_t)(mBase + row) * NGL + nBase + cc * 8) = vv;
        }
    } else {
        // ---------- epilogue: fold + residual (hoisted invariants) ----------
        int    pcol[8];
        float2 bv[8];
#pragma unroll
        for (int nt = 0; nt < 8; ++nt) {
            const int col = nBase + wn * 64 + nt * 8 + 2 * tig;
            bv[nt] = make_float2(__ldg(&bias[col]), __ldg(&bias[col + 1]));
            const int cg  = col >> 8;
            const int rem = col & 255;
            const int ph  = rem >> 4;
            const int pw  = rem & 15;
            pcol[nt] = cg * 147456 + ph * 384 + pw;
        }
        const int rowBand = mBase + wm * 64;
        const int bimg = rowBand / 576;      // 64-aligned band, 576 = 9*64
        const int lb   = rowBand - bimg * 576;

#pragma unroll
        for (int mt = 0; mt < 4; ++mt) {
#pragma unroll
            for (int half = 0; half < 2; ++half) {
                const int l  = lb + mt * 16 + g + half * 8;
                const int hp = l / 24;
                const int wp = l - hp * 24;
                const size_t rowOff = (size_t)bimg * 442368 + hp * 6144 + wp * 16;
#pragma unroll
                for (int nt = 0; nt < 8; ++nt) {
                    const size_t oi = rowOff + (size_t)pcol[nt];
                    const float2 xv = *(const float2*)(x + oi);
                    float2 v;
                    v.x = xv.x + acc[mt][nt][half * 2 + 0] + bv[nt].x;
                    v.y = xv.y + acc[mt][nt][half * 2 + 1] + bv[nt].y;
                    *(float2*)(out + oi) = v;
                }
            }
        }
    }
}

extern "C" void kernel_launch(void* const* d_in, const int* in_sizes, int n_in,
                              void* d_out, int out_size) {
    const float* x    = (const float*)d_in[0];
    const float* ln_w = (const float*)d_in[1];
    const float* ln_b = (const float*)d_in[2];
    const float* w1   = (const float*)d_in[3];
    const float* b1   = (const float*)d_in[4];
    const float* w2   = (const float*)d_in[5];
    const float* b2   = (const float*)d_in[6];
    float* out        = (float*)d_out;

    static bool configured = false;
    if (!configured) {
        cudaFuncSetAttribute(mma_gemm_kernel<HID, PS, 0>,
                             cudaFuncAttributeMaxDynamicSharedMemorySize, SMEM_BYTES);
        cudaFuncSetAttribute(mma_gemm_kernel<PS, HID, 1>,
                             cudaFuncAttributeMaxDynamicSharedMemorySize, SMEM_BYTES);
        configured = true;
    }

    dim3 tb(32, 8);
    transpose_kernel<0><<<dim3(HID / 32, PS / 32), tb>>>(w1, PS, HID);
    transpose_kernel<1><<<dim3(PS / 32, HID / 32), tb>>>(w2, HID, PS);

    patch_ln_kernel<<<TOKENS / 4, 128>>>(x, ln_w, ln_b);

    dim3 g1(HID / BN, TOKENS / BM);   // (12, 288)
    mma_gemm_kernel<HID, PS, 0><<<g1, GTHREADS, SMEM_BYTES>>>(b1, nullptr, nullptr);

    dim3 g2(PS / BN, TOKENS / BM);    // (6, 288)
    mma_gemm_kernel<PS, HID, 1><<<g2, GTHREADS, SMEM_BYTES>>>(b2, x, out);
}